// round 1
// baseline (speedup 1.0000x reference)
#include <cuda_runtime.h>

#define B_   4
#define CIN  256
#define CO   128
#define HI   64
#define WI   64
#define HO   128
#define WO   128

// Scratch: intermediate y, pre-transposed weights.
__device__ float g_y[B_ * CO * HO * WO];            // 32 MB
__device__ float g_w1t[4 * CIN * 4 * CO];           // [parity][c][tap][o]
__device__ float g_w2t[CO * 9 * CO];                // [c][tap][o]

// ---------------------------------------------------------------------------
// Weight pre-transpose kernels (trivial cost, run every launch — deterministic)
// ---------------------------------------------------------------------------
__global__ void prep_w1_kernel(const float* __restrict__ w1) {
    int idx = blockIdx.x * blockDim.x + threadIdx.x;
    const int total = 4 * CIN * 4 * CO;
    for (; idx < total; idx += gridDim.x * blockDim.x) {
        int o   = idx & 127;
        int tap = (idx >> 7) & 3;
        int c   = (idx >> 9) & 255;
        int par = idx >> 17;
        int ph = par >> 1, pw = par & 1;
        int a  = tap >> 1, bb = tap & 1;
        int kh = 2 * a + 1 - ph;    // tap->kernel row (conv_transpose, s=2,p=1,k=4)
        int kw = 2 * bb + 1 - pw;
        g_w1t[idx] = w1[((c * CO + o) * 4 + kh) * 4 + kw];
    }
}

__global__ void prep_w2_kernel(const float* __restrict__ w2) {
    int idx = blockIdx.x * blockDim.x + threadIdx.x;
    const int total = CO * 9 * CO;
    for (; idx < total; idx += gridDim.x * blockDim.x) {
        int c   = idx / 1152;
        int rem = idx - c * 1152;
        int tap = rem >> 7;          // 0..8
        int o   = rem & 127;
        int i = tap / 3, j = tap % 3;
        // wk[o,c,i,j] = w2[c,o,2-i,2-j]
        g_w2t[idx] = w2[(c * CO + o) * 9 + (2 - i) * 3 + (2 - j)];
    }
}

// ---------------------------------------------------------------------------
// Stage 1: conv_transpose 4x4 stride 2 pad 1, decomposed into 4 subpixel
// parities. Block: 128 out-ch x (8x16) output-parity-pixel tile, 256 threads,
// each thread owns an 8(o) x 8(px) register tile.
// ---------------------------------------------------------------------------
__global__ __launch_bounds__(256) void deconv_kernel(const float* __restrict__ x,
                                                     const float* __restrict__ b1) {
    __shared__ float xs[8 * 9 * 17];    // [c][r*17+s], pitch 17 (odd -> conflict-free)
    __shared__ float ws[8 * 4 * 128];   // [c][tap][o]

    const int tid  = threadIdx.x;
    const int bz   = blockIdx.z;
    const int bimg = bz >> 2;
    const int par  = bz & 3;
    const int ph = par >> 1, pw = par & 1;
    const int th0 = blockIdx.y * 8;
    const int tw0 = blockIdx.x * 16;

    const int og8   = (tid >> 4) * 8;
    const int pg    = tid & 15;
    const int prow  = pg >> 1;
    const int pcol8 = (pg & 1) * 8;

    const int base_h = th0 - 1 + ph;
    const int base_w = tw0 - 1 + pw;

    const float* wsrc = g_w1t + par * (CIN * 4 * CO);
    const float* xsrc = x + bimg * (CIN * HI * WI);

    float acc[8][8];
#pragma unroll
    for (int a = 0; a < 8; ++a)
#pragma unroll
        for (int b = 0; b < 8; ++b) acc[a][b] = 0.f;

    for (int c0 = 0; c0 < CIN; c0 += 8) {
        // weights: contiguous 4096 floats in pre-transposed layout -> float4 copy
        {
            const float4* src = (const float4*)(wsrc + c0 * 512);
            float4* dst = (float4*)ws;
            for (int e = tid; e < 1024; e += 256) dst[e] = src[e];
        }
        // x halo tile: 8c x 9 x 17, zero-padded
        for (int e = tid; e < 8 * 153; e += 256) {
            int c = e / 153;
            int rem = e - c * 153;
            int r = rem / 17, s = rem - r * 17;
            int ih = base_h + r, iw = base_w + s;
            float v = 0.f;
            if ((unsigned)ih < 64u && (unsigned)iw < 64u)
                v = xsrc[((c0 + c) * HI + ih) * WI + iw];
            xs[e] = v;
        }
        __syncthreads();

#pragma unroll 1
        for (int c = 0; c < 8; ++c) {
#pragma unroll
            for (int tap = 0; tap < 4; ++tap) {
                const int a  = tap >> 1;
                const int bb = tap & 1;
                const float* wrow = ws + (c * 4 + tap) * 128 + og8;
                float4 wA = *(const float4*)wrow;
                float4 wB = *(const float4*)(wrow + 4);
                float wv[8] = {wA.x, wA.y, wA.z, wA.w, wB.x, wB.y, wB.z, wB.w};
                const float* xrow = xs + c * 153 + (prow + 1 - a) * 17 + (pcol8 + 1 - bb);
                float xv[8];
#pragma unroll
                for (int jj = 0; jj < 8; ++jj) xv[jj] = xrow[jj];
#pragma unroll
                for (int oo = 0; oo < 8; ++oo)
#pragma unroll
                    for (int jj = 0; jj < 8; ++jj)
                        acc[oo][jj] = fmaf(wv[oo], xv[jj], acc[oo][jj]);
            }
        }
        __syncthreads();
    }

    const int oh = 2 * (th0 + prow) + ph;
#pragma unroll
    for (int oo = 0; oo < 8; ++oo) {
        int o = og8 + oo;
        float bias = __ldg(&b1[o]);
        float* ydst = g_y + ((bimg * CO + o) * HO + oh) * WO;
#pragma unroll
        for (int jj = 0; jj < 8; ++jj) {
            int ow = 2 * (tw0 + pcol8 + jj) + pw;
            ydst[ow] = acc[oo][jj] + bias;
        }
    }
}

// ---------------------------------------------------------------------------
// Stage 2: PAC conv_transpose 3x3 s1 p1.
// Phase A: k[tap][px] = exp(-0.5 * sum_c (guide_nb - guide_ctr)^2) in smem.
// Phase B: out[o,px] = sum_{tap,c} w2t[c,tap,o] * k[tap,px] * y[c, px+tap].
// Block: 128 out-ch x (8x16) pixel tile, 256 threads, 8x8 reg tile each.
// ---------------------------------------------------------------------------
__global__ __launch_bounds__(256) void pac_kernel(const float* __restrict__ guide,
                                                  const float* __restrict__ b2,
                                                  float* __restrict__ out) {
    __shared__ float tile[8 * 190];     // [c][r*19+s], r<10, s<18 used (pitch 19)
    __shared__ float ksm[9 * 128];      // [tap][px]
    __shared__ float wt[8 * 9 * 128];   // [c][tap][o]

    const int tid  = threadIdx.x;
    const int bimg = blockIdx.z;
    const int h0   = blockIdx.y * 8;
    const int w0   = blockIdx.x * 16;

    const int og8   = (tid >> 4) * 8;
    const int pg    = tid & 15;
    const int prow  = pg >> 1;
    const int pcol8 = (pg & 1) * 8;

    const float* gsrc = guide + bimg * (CO * HO * WO);
    const float* ysrc = g_y   + bimg * (CO * HO * WO);

    // ---- Phase A: Gaussian kernel weights ----
    float ssd[5] = {0.f, 0.f, 0.f, 0.f, 0.f};
    for (int c0 = 0; c0 < CO; c0 += 8) {
        for (int e = tid; e < 8 * 190; e += 256) {
            int c = e / 190;
            int rem = e - c * 190;
            int r = rem / 19, s = rem - r * 19;
            int gh = h0 - 1 + r, gw = w0 - 1 + s;
            float v = 0.f;
            if ((unsigned)gh < 128u && (unsigned)gw < 128u)
                v = gsrc[((c0 + c) * HO + gh) * WO + gw];
            tile[e] = v;
        }
        __syncthreads();
#pragma unroll
        for (int t = 0; t < 5; ++t) {
            int task = tid + t * 256;
            if (task < 1152) {
                int tap = task >> 7;
                int px  = task & 127;
                int i = tap / 3, j = tap - i * 3;
                int pr = px >> 4, pc = px & 15;
                float s_ = ssd[t];
#pragma unroll
                for (int c = 0; c < 8; ++c) {
                    float ctr = tile[c * 190 + (pr + 1) * 19 + pc + 1];
                    float nb  = tile[c * 190 + (pr + i) * 19 + pc + j];
                    float d = nb - ctr;
                    s_ = fmaf(d, d, s_);
                }
                ssd[t] = s_;
            }
        }
        __syncthreads();
    }
#pragma unroll
    for (int t = 0; t < 5; ++t) {
        int task = tid + t * 256;
        if (task < 1152) ksm[task] = __expf(-0.5f * ssd[t]);
    }
    __syncthreads();

    // ---- Phase B: main GEMM ----
    float acc[8][8];
#pragma unroll
    for (int a = 0; a < 8; ++a)
#pragma unroll
        for (int b = 0; b < 8; ++b) acc[a][b] = 0.f;

    for (int c0 = 0; c0 < CO; c0 += 8) {
        for (int e = tid; e < 8 * 190; e += 256) {
            int c = e / 190;
            int rem = e - c * 190;
            int r = rem / 19, s = rem - r * 19;
            int yh = h0 - 1 + r, yw = w0 - 1 + s;
            float v = 0.f;
            if ((unsigned)yh < 128u && (unsigned)yw < 128u)
                v = ysrc[((c0 + c) * HO + yh) * WO + yw];
            tile[e] = v;
        }
        {
            const float4* src = (const float4*)(g_w2t + c0 * 1152);
            float4* dst = (float4*)wt;
            for (int e = tid; e < 2304; e += 256) dst[e] = src[e];
        }
        __syncthreads();

#pragma unroll 1
        for (int tap = 0; tap < 9; ++tap) {
            const int i = tap / 3, j = tap - i * 3;
            float kv[8];
#pragma unroll
            for (int jj = 0; jj < 8; ++jj)
                kv[jj] = ksm[tap * 128 + prow * 16 + pcol8 + jj];
#pragma unroll 1
            for (int c = 0; c < 8; ++c) {
                const float* wrow = wt + (c * 9 + tap) * 128 + og8;
                float4 wA = *(const float4*)wrow;
                float4 wB = *(const float4*)(wrow + 4);
                float wv[8] = {wA.x, wA.y, wA.z, wA.w, wB.x, wB.y, wB.z, wB.w};
                const float* yrow = tile + c * 190 + (prow + i) * 19 + (pcol8 + j);
                float yk[8];
#pragma unroll
                for (int jj = 0; jj < 8; ++jj) yk[jj] = yrow[jj] * kv[jj];
#pragma unroll
                for (int oo = 0; oo < 8; ++oo)
#pragma unroll
                    for (int jj = 0; jj < 8; ++jj)
                        acc[oo][jj] = fmaf(wv[oo], yk[jj], acc[oo][jj]);
            }
        }
        __syncthreads();
    }

    const int h = h0 + prow;
#pragma unroll
    for (int oo = 0; oo < 8; ++oo) {
        int o = og8 + oo;
        float bias = __ldg(&b2[o]);
        float* dst = out + ((bimg * CO + o) * HO + h) * WO + w0 + pcol8;
#pragma unroll
        for (int jj = 0; jj < 8; ++jj) dst[jj] = acc[oo][jj] + bias;
    }
}

// ---------------------------------------------------------------------------
extern "C" void kernel_launch(void* const* d_in, const int* in_sizes, int n_in,
                              void* d_out, int out_size) {
    const float* x     = (const float*)d_in[0];
    const float* guide = (const float*)d_in[1];
    const float* w1    = (const float*)d_in[2];
    const float* b1    = (const float*)d_in[3];
    const float* w2    = (const float*)d_in[4];
    const float* b2    = (const float*)d_in[5];
    float* out = (float*)d_out;

    prep_w1_kernel<<<512, 256>>>(w1);
    prep_w2_kernel<<<288, 256>>>(w2);
    deconv_kernel<<<dim3(4, 8, 16), 256>>>(x, b1);
    pac_kernel<<<dim3(8, 16, 4), 256>>>(guide, b2, out);
}